// round 11
// baseline (speedup 1.0000x reference)
#include <cuda_runtime.h>
#include <cuda_bf16.h>
#include <math.h>

#define B_ 32
#define T_ 64
#define N_ 128
#define D_ 64
#define K2 129              // 2D+1 (source layout)
#define KD (K2*D_)          // 8256 (source stride)
#define KR 132              // padded k rows: [x 0..63 | rs 64 | pad 65..67 | h 68..131]
#define KD132 (KR*D_)       // 8448
#define HSZ (B_*N_*D_)
#define GRID 128
#define BLOCK 1024

// ---- smem layout (floats) ----
// persistent weights + bias
#define OFF_W     0                    // 3*KD132 = 25344 (Wt[g][d][k], k-contig)
#define OFF_BEFF  (3*KD132)            // 192
// UNION scratch (Phase A and Phase B non-persistent share this)
#define U_OFF     (3*KD132 + 192)      // 25536, size 21256
//   Phase A (rel U_OFF): feat 0..16896, wT 16896..20992, rsv 20992..21120,
//                        list 21120(int), cnt 21248..21256(int)
//   Phase B (rel U_OFF): combs 0..4224, usB 4224..6272, cxsB 6272..8320,
//                        listB 8320(int), listU 8352(int), lenS 8384(int), pnB 8416(int)
#define U_SIZE    21256
// persistent Phase B state (survives Phase A)
#define HS_OFF    (U_OFF + U_SIZE)     // 46792, size 2048  (h state per b,d)
#define ZCS_OFF   (HS_OFF + 2048)      // 48840, size 4224  (x|rs|pad|h1, prefetched)
#define SMEM_FLOATS (ZCS_OFF + 4224)   // 53064
#define SMEM_BYTES  (SMEM_FLOATS*4 + 64)   // 212320 B <= 227KB

__device__ float g_invtot[B_*N_];
__device__ float g_hbuf[2*HSZ];
__device__ float g_comb[B_*N_*KR];   // pad cols (65..67) stay zero
__device__ float g_P[N_*N_];         // P[j][i] = adjI[i][j]
__device__ float g_Q[N_*N_];         // Q[j][i] = adjI[i][j]*rarW[i][j]

// ---- two-level grid barrier ----
__device__ unsigned int g_cnt[8*32];
__device__ unsigned int g_rootc;
__device__ volatile unsigned int g_gen;

__device__ __forceinline__ void grid_barrier() {
    __syncthreads();
    if (threadIdx.x == 0) {
        __threadfence();
        unsigned int gen = g_gen;
        unsigned int grp = blockIdx.x >> 4;
        unsigned int o = atomicAdd(&g_cnt[grp*32], 1u);
        if ((o & 15u) == 15u) {
            unsigned int r = atomicAdd(&g_rootc, 1u);
            if ((r & 7u) == 7u) {
                __threadfence();
                g_gen = gen + 1u;
            }
        }
        while (g_gen == gen) { }
        __threadfence();
    }
    __syncthreads();
}

__device__ __forceinline__ float tanhfast(float x) {
    float y;
    asm("tanh.approx.f32 %0, %1;" : "=f"(y) : "f"(x));
    return y;
}
__device__ __forceinline__ float sigfast(float x) {
    return fmaf(tanhfast(0.5f*x), 0.5f, 0.5f);
}

// ---- packed dual-FMA (sm_103a FFMA2, PTX-only) ----
typedef unsigned long long ull;
__device__ __forceinline__ ull ffma2_(ull a, ull b, ull c) {
    ull d;
    asm("fma.rn.f32x2 %0, %1, %2, %3;" : "=l"(d) : "l"(a), "l"(b), "l"(c));
    return d;
}
__device__ __forceinline__ float hsum2_(ull a) {
    float lo, hi;
    asm("mov.b64 {%0, %1}, %2;" : "=f"(lo), "=f"(hi) : "l"(a));
    return lo + hi;
}
__device__ __forceinline__ ull pack1_(float lo) {
    ull d;
    asm("mov.b64 %0, {%1, %2};" : "=l"(d) : "f"(lo), "f"(0.0f));
    return d;
}

__global__ void __launch_bounds__(BLOCK, 1)
cgrnn_persistent(const float* __restrict__ obs,      // [B,T,N,D]
                 const float* __restrict__ mask,     // [B,T,N]
                 const int*   __restrict__ lengths,  // [B]
                 const float* __restrict__ avg,      // [B,T,N]
                 const float* __restrict__ vpe,      // [N,768]
                 const float* __restrict__ rarW,     // [N,N]
                 const float* __restrict__ adjI,     // [N,N]
                 const float* __restrict__ W1,       // [768,128]
                 const float* __restrict__ b1,       // [128]
                 const float* __restrict__ W2,       // [128,5]
                 const float* __restrict__ b2,       // [5]
                 const float* __restrict__ Wr, const float* __restrict__ brp,
                 const float* __restrict__ Wu, const float* __restrict__ bup,
                 const float* __restrict__ Wc, const float* __restrict__ bcp,
                 float* __restrict__ out)            // [B,N,D]
{
    extern __shared__ char smem_raw[];
    float* sm = (float*)smem_raw;
    float* Wst    = sm + OFF_W;
    float* beff_s = sm + OFF_BEFF;
    float* scrU   = sm + U_OFF;
    float* hsB    = sm + HS_OFF;    // persistent [32][64]
    float* zcs    = sm + ZCS_OFF;   // persistent [32][132]
    const int tid  = threadIdx.x;
    const int bid  = blockIdx.x;
    const int warp = tid >> 5;
    const int lane = tid & 31;
    const int n_node = bid;

    // Phase B union aliases
    float* combs = scrU + 0;              // [32][132]
    float* usB   = scrU + 4224;           // [32][64]
    float* cxsB  = scrU + 6272;           // [32][64]
    int*   listB = (int*)(scrU + 8320);
    int*   listU = (int*)(scrU + 8352);
    int*   lenS  = (int*)(scrU + 8384);
    int*   pnB   = (int*)(scrU + 8416);

    // ========== P1: hypernetwork vv for this node ==========
    {
        float* part = scrU;
        float* hid  = scrU + 1024;
        float* vvs  = scrU + 1152;
        int q = tid >> 7, col = tid & 127;
        const float* vrow = vpe + n_node*768;
        float acc = 0.0f;
        int k0 = q * 96;
        #pragma unroll 4
        for (int k = k0; k < k0 + 96; k++)
            acc = fmaf(vrow[k], W1[k*128 + col], acc);
        part[tid] = acc;
        __syncthreads();
        if (tid < 128) {
            float h = b1[tid];
            #pragma unroll
            for (int qq = 0; qq < 8; qq++) h += part[qq*128 + tid];
            hid[tid] = fmaxf(h, 0.0f);
        }
        __syncthreads();
        if (tid < 5) {
            float a = b2[tid];
            for (int d = 0; d < 128; d++)
                a = fmaf(hid[d], W2[d*5 + tid], a);
            vvs[tid] = a;
        }
        __syncthreads();

        // ===== P2a: effective weights, TRANSPOSED Wt[g][d][k], k padded =====
        float v0 = vvs[0], v1 = vvs[1], v2 = vvs[2], v3 = vvs[3], v4 = vvs[4];
        __syncthreads();
        for (int idx = tid; idx < 3*KD132; idx += BLOCK) {
            int g  = idx / KD132;
            int kd = idx - g*KD132;
            int kk = kd >> 6;     // padded k 0..131
            int d  = kd & 63;
            float a = 0.0f;
            if (kk < 65 || kk >= 68) {
                int ko = (kk < 65) ? kk : (kk - 3);
                const float* src = (g == 0) ? Wr : (g == 1) ? Wu : Wc;
                int off = ko*64 + d;
                a = v0 * src[off];
                a = fmaf(v1, src[KD + off], a);
                a = fmaf(v2, src[2*KD + off], a);
                a = fmaf(v3, src[3*KD + off], a);
                a = fmaf(v4, src[4*KD + off], a);
            }
            Wst[g*KD132 + d*132 + kk] = a;
        }
        for (int idx = tid; idx < 3*D_; idx += BLOCK) {
            int g = idx >> 6;
            int d = idx & 63;
            const float* src = (g == 0) ? brp : (g == 1) ? bup : bcp;
            float a = v0 * src[d];
            a = fmaf(v1, src[D_ + d], a);
            a = fmaf(v2, src[2*D_ + d], a);
            a = fmaf(v3, src[3*D_ + d], a);
            a = fmaf(v4, src[4*D_ + d], a);
            beff_s[idx] = a;
        }
    }

    // ===== P2b: inv_tot, P/Q transpose, zero h0, init persistent state =====
    {
        for (int k = tid; k < 32; k += BLOCK) {
            int idx = bid*32 + k;
            int b = idx >> 7;
            int n = idx & 127;
            float s = 0.0f;
            for (int t = 0; t < T_; t++) s += mask[(b*T_ + t)*N_ + n];
            g_invtot[idx] = 1.0f / (s + 1.0f);
        }
        for (int idx = bid*BLOCK + tid; idx < N_*N_; idx += GRID*BLOCK) {
            int j = idx >> 7, i = idx & 127;
            float a = adjI[i*N_ + j];
            g_P[idx] = a;
            g_Q[idx] = a * rarW[i*N_ + j];
        }
        for (int idx = bid*BLOCK + tid; idx < HSZ; idx += GRID*BLOCK)
            g_hbuf[idx] = 0.0f;
        for (int idx = tid; idx < B_*D_; idx += BLOCK) hsB[idx] = 0.0f;
        // stage step-0 zcs x + rs + pads (needs g_invtot for THIS node's rows:
        // computed by this block above: idx = bid*32+k covers b=k>>2? no —
        // g_invtot[b*128+n] for n=bid needs blocks (b*128+bid)/32 — not local.
        // So compute rs via direct formula after a grid barrier instead.)
        for (int idx = tid; idx < B_*16; idx += BLOCK) {
            int b = idx >> 4, qq = idx & 15;
            *(float4*)(zcs + b*KR + qq*4) =
                *(const float4*)(obs + (size_t)((b*T_)*N_ + n_node)*D_ + qq*4);
        }
        if (tid < 32) {
            float* zr = zcs + tid*KR;
            zr[65] = 0.0f; zr[66] = 0.0f; zr[67] = 0.0f;
        }
    }
    grid_barrier();
    // g_invtot now globally visible: finish step-0 rs staging
    if (tid < 32) {
        zcs[tid*KR + 64] =
            0.5f * tanhfast(avg[(tid*T_)*N_ + n_node] * g_invtot[tid*N_ + n_node]);
    }
    __syncthreads();

    // ========== time loop ==========
    for (int t = 0; t < T_; t++) {
        const float* hprev = g_hbuf + (t & 1) * HSZ;
        float*       hnext = g_hbuf + ((t + 1) & 1) * HSZ;

        // ---------------- Phase A ----------------
        {
            const int b = bid >> 2;
            const int q = bid & 3;
            float* feat = scrU + 0;
            float* wT   = scrU + 16896;
            float* rsv  = scrU + 20992;
            int*   list = (int*)(scrU + 21120);
            int*   cnt  = (int*)(scrU + 21248);

            if (tid < 128) {
                float m = mask[(b*T_ + t)*N_ + tid];
                rsv[tid] = 0.5f * tanhfast(avg[(b*T_ + t)*N_ + tid] * g_invtot[b*N_ + tid]);
                bool ob = (m != 0.0f);
                unsigned msk = __ballot_sync(0xffffffffu, ob);
                if (lane == 0) { cnt[warp] = __popc(msk); ((unsigned*)cnt)[4 + warp] = msk; }
            }
            __syncthreads();
            const int nobs = cnt[0] + cnt[1] + cnt[2] + cnt[3];
            if (tid < 128) {
                unsigned msk = ((unsigned*)cnt)[4 + warp];
                if ((msk >> lane) & 1u) {
                    int off = __popc(msk & ((1u << lane) - 1u));
                    for (int ww = 0; ww < warp; ww++) off += cnt[ww];
                    list[off] = tid;
                }
            }
            __syncthreads();

            const int lo  = (nobs * q) >> 2;
            const int hi  = (nobs * (q + 1)) >> 2;
            const int myn = hi - lo;

            // stage feat: x 0..63 | rs 64 | pads 65..67 | h 68..131
            for (int idx = tid; idx < nobs*16; idx += BLOCK) {
                int jc = idx >> 4, qq = idx & 15;
                int j = list[jc];
                *(float4*)(feat + jc*KR + qq*4) =
                    *(const float4*)(obs + (size_t)((b*T_ + t)*N_ + j)*D_ + qq*4);
            }
            for (int idx = tid; idx < nobs*16; idx += BLOCK) {
                int jc = idx >> 4, qq = idx & 15;
                int j = list[jc];
                *(float4*)(feat + jc*KR + 68 + qq*4) =
                    *(const float4*)(hprev + (size_t)(b*N_ + j)*D_ + qq*4);
            }
            if (tid < nobs) {
                float* fr = feat + tid*KR;
                fr[64] = rsv[list[tid]];
                fr[65] = 0.0f; fr[66] = 0.0f; fr[67] = 0.0f;
            }
            // stage wT[jc][ic] (lane = ic, conflict-free)
            {
                int jc0 = warp;
                int ic  = lane;
                int i   = (ic < myn) ? list[lo + ic] : 0;
                float rsi = rsv[i];
                bool valid = (ic < myn);
                for (int jc = jc0; jc < nobs; jc += 32) {
                    int j = list[jc];
                    float wv = 0.0f;
                    if (valid) {
                        if (j == i) wv = 1.0f;
                        else wv = g_P[j*N_ + i] - g_Q[j*N_ + i] * fabsf(rsi - rsv[j]);
                    }
                    wT[jc*32 + ic] = wv;
                }
            }
            __syncthreads();

            // GEMM: 2-row x 2-col tiles over 66 padded col-pairs (<=1024 tasks)
            const int RG2 = (myn + 1) >> 1;
            for (int tt = tid; tt < RG2*66; tt += BLOCK) {
                int rg = tt / 66;
                int e  = tt - rg*66;
                int c0 = e*2;
                const float* wp = wT + rg*2;
                const float* fp = feat + c0;
                float ax = 0.f, ay = 0.f, bx = 0.f, by = 0.f;
                #pragma unroll 4
                for (int jc = 0; jc < nobs; jc++) {
                    float2 w2 = *(const float2*)(wp + jc*32);
                    float2 f2 = *(const float2*)(fp + jc*KR);
                    ax = fmaf(w2.x, f2.x, ax); ay = fmaf(w2.x, f2.y, ay);
                    bx = fmaf(w2.y, f2.x, bx); by = fmaf(w2.y, f2.y, by);
                }
                int ic0 = rg*2;
                {
                    int i = list[lo + ic0];
                    *(float2*)&g_comb[(size_t)(b*N_ + i)*KR + c0] = make_float2(ax, ay);
                }
                if (ic0 + 1 < myn) {
                    int i1 = list[lo + ic0 + 1];
                    *(float2*)&g_comb[(size_t)(b*N_ + i1)*KR + c0] = make_float2(bx, by);
                }
            }
        }
        grid_barrier();

        // ---------------- Phase B ----------------
        {
            const int n = n_node;

            if (tid < 32) {
                int b = tid;
                float m = mask[(b*T_ + t)*N_ + n];
                lenS[b] = lengths[b];
                bool ob = (m != 0.0f);
                unsigned msk = __ballot_sync(0xffffffffu, ob);
                unsigned msku = ~msk;
                if (ob) listB[__popc(msk & ((1u << tid) - 1u))] = b;
                else    listU[__popc(msku & ((1u << tid) - 1u))] = b;
                if (tid == 0) *pnB = __popc(msk);
            }
            __syncthreads();
            const int nB = *pnB;
            const int BQ  = (nB + 3) >> 2;
            const int BO  = (nB + 7) >> 3;
            const int BP2 = (nB + 1) >> 1;

            for (int idx = tid; idx < nB*33; idx += BLOCK) {
                int bc = idx / 33;
                int qq = idx - bc*33;
                int b  = listB[bc];
                *(float4*)(combs + b*KR + qq*4) =
                    *(const float4*)(g_comb + (size_t)(b*N_ + n)*KR + qq*4);
            }
            __syncthreads();

            // ---- pass1 warp-tasks (r/u quads first; candx octets after) ----
            const int NT_RU = 4*BQ;
            const int NT1 = NT_RU + 2*BO;
            for (int tau = warp; tau < NT1; tau += 32) {
                if (tau < NT_RU) {
                    int bq  = tau >> 2;
                    int sub = tau & 3;
                    int g   = sub >> 1;          // 0=r, 1=u
                    int dh  = sub & 1;
                    int d   = dh*32 + lane;
                    int b0 = listB[min(4*bq + 0, nB - 1)];
                    int b1 = listB[min(4*bq + 1, nB - 1)];
                    int b2 = listB[min(4*bq + 2, nB - 1)];
                    int b3 = listB[min(4*bq + 3, nB - 1)];
                    const ulonglong2* Wp = (const ulonglong2*)(Wst + g*KD132 + d*132);
                    const ulonglong2* p0 = (const ulonglong2*)(combs + b0*KR);
                    const ulonglong2* p1 = (const ulonglong2*)(combs + b1*KR);
                    const ulonglong2* p2 = (const ulonglong2*)(combs + b2*KR);
                    const ulonglong2* p3 = (const ulonglong2*)(combs + b3*KR);
                    ull a0 = pack1_(beff_s[g*64 + d]);
                    ull a1 = a0, a2 = a0, a3 = a0;
                    #pragma unroll 3
                    for (int k4 = 0; k4 < 33; k4++) {
                        ulonglong2 w  = Wp[k4];
                        ulonglong2 c0 = p0[k4], c1 = p1[k4], c2 = p2[k4], c3 = p3[k4];
                        a0 = ffma2_(c0.x, w.x, a0); a0 = ffma2_(c0.y, w.y, a0);
                        a1 = ffma2_(c1.x, w.x, a1); a1 = ffma2_(c1.y, w.y, a1);
                        a2 = ffma2_(c2.x, w.x, a2); a2 = ffma2_(c2.y, w.y, a2);
                        a3 = ffma2_(c3.x, w.x, a3); a3 = ffma2_(c3.y, w.y, a3);
                    }
                    float s0 = hsum2_(a0), s1 = hsum2_(a1), s2 = hsum2_(a2), s3 = hsum2_(a3);
                    if (g == 0) {
                        zcs[b0*KR + 68 + d] = sigfast(s0) * hsB[b0*64 + d];
                        zcs[b1*KR + 68 + d] = sigfast(s1) * hsB[b1*64 + d];
                        zcs[b2*KR + 68 + d] = sigfast(s2) * hsB[b2*64 + d];
                        zcs[b3*KR + 68 + d] = sigfast(s3) * hsB[b3*64 + d];
                    } else {
                        usB[b0*64 + d] = sigfast(s0);
                        usB[b1*64 + d] = sigfast(s1);
                        usB[b2*64 + d] = sigfast(s2);
                        usB[b3*64 + d] = sigfast(s3);
                    }
                } else {
                    // candx octet: k = 0..64 on raw [x|rs]
                    int t2 = tau - NT_RU;
                    int bo = t2 >> 1;
                    int dh = t2 & 1;
                    int d  = dh*32 + lane;
                    int bb[8];
                    #pragma unroll
                    for (int i = 0; i < 8; i++) bb[i] = listB[min(8*bo + i, nB - 1)];
                    const float*      Wrow = Wst + 2*KD132 + d*132;
                    const ulonglong2* Wp   = (const ulonglong2*)Wrow;
                    ull acc[8];
                    {
                        ull binit = pack1_(beff_s[2*64 + d]);
                        #pragma unroll
                        for (int i = 0; i < 8; i++) acc[i] = binit;
                    }
                    #pragma unroll 2
                    for (int k4 = 0; k4 < 16; k4++) {
                        ulonglong2 w = Wp[k4];
                        #pragma unroll
                        for (int i = 0; i < 8; i++) {
                            ulonglong2 c = ((const ulonglong2*)(zcs + bb[i]*KR))[k4];
                            acc[i] = ffma2_(c.x, w.x, acc[i]);
                            acc[i] = ffma2_(c.y, w.y, acc[i]);
                        }
                    }
                    float wrs = Wrow[64];
                    #pragma unroll
                    for (int i = 0; i < 8; i++) {
                        float s = hsum2_(acc[i]);
                        s = fmaf(zcs[bb[i]*KR + 64], wrs, s);
                        cxsB[bb[i]*64 + d] = s;
                    }
                }
            }
            __syncthreads();

            // ---- pass2: candh on batch-pairs; carry pairs after ----
            const int NT2 = 2*BP2 + ((B_ - nB + 1) >> 1);
            for (int tau = warp; tau < NT2; tau += 32) {
                if (tau < 2*BP2) {
                    int bp = tau >> 1;
                    int dh = tau & 1;
                    int d  = dh*32 + lane;
                    int b0 = listB[2*bp];
                    int b1 = listB[min(2*bp + 1, nB - 1)];
                    const ulonglong2* Wp = (const ulonglong2*)(Wst + 2*KD132 + d*132 + 68);
                    const ulonglong2* p0 = (const ulonglong2*)(zcs + b0*KR + 68);
                    const ulonglong2* p1 = (const ulonglong2*)(zcs + b1*KR + 68);
                    ull a0 = pack1_(cxsB[b0*64 + d]);
                    ull a1 = pack1_(cxsB[b1*64 + d]);
                    #pragma unroll 4
                    for (int k4 = 0; k4 < 16; k4++) {
                        ulonglong2 w  = Wp[k4];
                        ulonglong2 c0 = p0[k4], c1 = p1[k4];
                        a0 = ffma2_(c0.x, w.x, a0); a0 = ffma2_(c0.y, w.y, a0);
                        a1 = ffma2_(c1.x, w.x, a1); a1 = ffma2_(c1.y, w.y, a1);
                    }
                    float A0 = hsum2_(a0), A1 = hsum2_(a1);
                    float h10 = zcs[b0*KR + 68 + d];
                    float h11 = zcs[b1*KR + 68 + d];
                    float u0  = usB[b0*64 + d];
                    float u1  = usB[b1*64 + d];
                    float v0 = h10 + u0 * (tanhfast(A0) - h10);
                    float v1 = h11 + u1 * (tanhfast(A1) - h11);
                    hnext[(size_t)(b0*N_ + n)*D_ + d] = v0;
                    hnext[(size_t)(b1*N_ + n)*D_ + d] = v1;
                    hsB[b0*64 + d] = v0;
                    hsB[b1*64 + d] = v1;
                    if (t == lenS[b0] - 1) out[(size_t)(b0*N_ + n)*D_ + d] = v0;
                    if (t == lenS[b1] - 1) out[(size_t)(b1*N_ + n)*D_ + d] = v1;
                } else {
                    int iu = (tau - 2*BP2) * 2;
                    int nU = B_ - nB;
                    #pragma unroll
                    for (int rep = 0; rep < 2; rep++) {
                        if (iu + rep < nU) {
                            int b = listU[iu + rep];
                            int d0 = lane*2;
                            float2 v = *(const float2*)(hsB + b*64 + d0);
                            *(float2*)(hnext + (size_t)(b*N_ + n)*D_ + d0) = v;
                            if (t == lenS[b] - 1)
                                *(float2*)(out + (size_t)(b*N_ + n)*D_ + d0) = v;
                        }
                    }
                }
            }
            // prefetch next step's zcs x + rs (disjoint from pass2's zcs reads)
            if (t + 1 < T_) {
                for (int idx = tid; idx < B_*16; idx += BLOCK) {
                    int b = idx >> 4, qq = idx & 15;
                    *(float4*)(zcs + b*KR + qq*4) =
                        *(const float4*)(obs + (size_t)((b*T_ + t + 1)*N_ + n)*D_ + qq*4);
                }
                if (tid < 32) {
                    zcs[tid*KR + 64] =
                        0.5f * tanhfast(avg[(tid*T_ + t + 1)*N_ + n] * g_invtot[tid*N_ + n]);
                }
            }
        }
        grid_barrier();
    }
}

extern "C" void kernel_launch(void* const* d_in, const int* in_sizes, int n_in,
                              void* d_out, int out_size) {
    const float* obs     = (const float*)d_in[0];
    const float* mask    = (const float*)d_in[2];
    const int*   lengths = (const int*)d_in[5];
    const float* avg     = (const float*)d_in[6];
    const float* vpe     = (const float*)d_in[7];
    const float* rarW    = (const float*)d_in[8];
    const float* adjI    = (const float*)d_in[9];
    const float* W1      = (const float*)d_in[10];
    const float* b1      = (const float*)d_in[11];
    const float* W2      = (const float*)d_in[12];
    const float* b2      = (const float*)d_in[13];
    const float* Wu      = (const float*)d_in[14];
    const float* bu      = (const float*)d_in[15];
    const float* Wr      = (const float*)d_in[16];
    const float* br      = (const float*)d_in[17];
    const float* Wc      = (const float*)d_in[18];
    const float* bc      = (const float*)d_in[19];
    float* out = (float*)d_out;

    cudaFuncSetAttribute(cgrnn_persistent,
                         cudaFuncAttributeMaxDynamicSharedMemorySize, SMEM_BYTES);
    cgrnn_persistent<<<GRID, BLOCK, SMEM_BYTES>>>(
        obs, mask, lengths, avg, vpe, rarW, adjI,
        W1, b1, W2, b2, Wr, br, Wu, bu, Wc, bc, out);
}

// round 12
// speedup vs baseline: 1.0701x; 1.0701x over previous
#include <cuda_runtime.h>
#include <cuda_bf16.h>
#include <math.h>

#define B_ 32
#define T_ 64
#define N_ 128
#define D_ 64
#define K2 129              // 2D+1 (source layout)
#define KD (K2*D_)          // 8256 (source stride)
#define KR 132              // padded k rows: [x 0..63 | rs 64 | pad 65..67 | h 68..131]
#define KD132 (KR*D_)       // 8448
#define HSZ (B_*N_*D_)
#define GRID 128
#define BLOCK 1024

// ---- smem layout (floats) ----
#define OFF_W     0                    // 3*KD132 = 25344 (W[g][k][d], k-major rows of 64)
#define OFF_BEFF  (3*KD132)            // 192
#define U_OFF     (3*KD132 + 192)      // union scratch, size 21256
//   Phase A (rel U_OFF): feat 0..16896, wT 16896..20992, rsv 20992..21120,
//                        list 21120(int), cnt 21248..21256(int)
//   Phase B (rel U_OFF): combs 0..4224, usB 4224..6272, cxsB 6272..8320,
//                        listB 8320(int), listU 8352(int), lenS 8384(int), pnB 8416(int)
#define U_SIZE    21256
#define HS_OFF    (U_OFF + U_SIZE)     // persistent h [32][64] = 2048
#define ZCS_OFF   (HS_OFF + 2048)      // persistent zcs [32][132] = 4224
#define SMEM_FLOATS (ZCS_OFF + 4224)
#define SMEM_BYTES  (SMEM_FLOATS*4 + 64)

__device__ float g_invtot[B_*N_];
__device__ float g_hbuf[2*HSZ];
__device__ float g_comb[B_*N_*KR];   // pad cols stay zero
__device__ float g_P[N_*N_];
__device__ float g_Q[N_*N_];

__device__ unsigned int g_cnt[8*32];
__device__ unsigned int g_rootc;
__device__ volatile unsigned int g_gen;

__device__ __forceinline__ void grid_barrier() {
    __syncthreads();
    if (threadIdx.x == 0) {
        __threadfence();
        unsigned int gen = g_gen;
        unsigned int grp = blockIdx.x >> 4;
        unsigned int o = atomicAdd(&g_cnt[grp*32], 1u);
        if ((o & 15u) == 15u) {
            unsigned int r = atomicAdd(&g_rootc, 1u);
            if ((r & 7u) == 7u) {
                __threadfence();
                g_gen = gen + 1u;
            }
        }
        while (g_gen == gen) { }
        __threadfence();
    }
    __syncthreads();
}

__device__ __forceinline__ float tanhfast(float x) {
    float y;
    asm("tanh.approx.f32 %0, %1;" : "=f"(y) : "f"(x));
    return y;
}
__device__ __forceinline__ float sigfast(float x) {
    return fmaf(tanhfast(0.5f*x), 0.5f, 0.5f);
}

__global__ void __launch_bounds__(BLOCK, 1)
cgrnn_persistent(const float* __restrict__ obs,      // [B,T,N,D]
                 const float* __restrict__ mask,     // [B,T,N]
                 const int*   __restrict__ lengths,  // [B]
                 const float* __restrict__ avg,      // [B,T,N]
                 const float* __restrict__ vpe,      // [N,768]
                 const float* __restrict__ rarW,     // [N,N]
                 const float* __restrict__ adjI,     // [N,N]
                 const float* __restrict__ W1,       // [768,128]
                 const float* __restrict__ b1,       // [128]
                 const float* __restrict__ W2,       // [128,5]
                 const float* __restrict__ b2,       // [5]
                 const float* __restrict__ Wr, const float* __restrict__ brp,
                 const float* __restrict__ Wu, const float* __restrict__ bup,
                 const float* __restrict__ Wc, const float* __restrict__ bcp,
                 float* __restrict__ out)            // [B,N,D]
{
    extern __shared__ char smem_raw[];
    float* sm = (float*)smem_raw;
    float* Wst    = sm + OFF_W;
    float* beff_s = sm + OFF_BEFF;
    float* scrU   = sm + U_OFF;
    float* hsB    = sm + HS_OFF;
    float* zcs    = sm + ZCS_OFF;
    const int tid  = threadIdx.x;
    const int bid  = blockIdx.x;
    const int warp = tid >> 5;
    const int lane = tid & 31;
    const int n_node = bid;

    float* combs = scrU + 0;
    float* usB   = scrU + 4224;
    float* cxsB  = scrU + 6272;
    int*   listB = (int*)(scrU + 8320);
    int*   listU = (int*)(scrU + 8352);
    int*   lenS  = (int*)(scrU + 8384);
    int*   pnB   = (int*)(scrU + 8416);

    // ========== P1: hypernetwork vv ==========
    {
        float* part = scrU;
        float* hid  = scrU + 1024;
        float* vvs  = scrU + 1152;
        int q = tid >> 7, col = tid & 127;
        const float* vrow = vpe + n_node*768;
        float acc = 0.0f;
        int k0 = q * 96;
        #pragma unroll 4
        for (int k = k0; k < k0 + 96; k++)
            acc = fmaf(vrow[k], W1[k*128 + col], acc);
        part[tid] = acc;
        __syncthreads();
        if (tid < 128) {
            float h = b1[tid];
            #pragma unroll
            for (int qq = 0; qq < 8; qq++) h += part[qq*128 + tid];
            hid[tid] = fmaxf(h, 0.0f);
        }
        __syncthreads();
        if (tid < 5) {
            float a = b2[tid];
            for (int d = 0; d < 128; d++)
                a = fmaf(hid[d], W2[d*5 + tid], a);
            vvs[tid] = a;
        }
        __syncthreads();

        // ===== P2a: effective weights W[g][k][d], padded k =====
        float v0 = vvs[0], v1 = vvs[1], v2 = vvs[2], v3 = vvs[3], v4 = vvs[4];
        __syncthreads();
        for (int idx = tid; idx < 3*KD132; idx += BLOCK) {
            int g  = idx / KD132;
            int kd = idx - g*KD132;
            int kk = kd >> 6;
            int d  = kd & 63;
            float a = 0.0f;
            if (kk < 65 || kk >= 68) {
                int ko = (kk < 65) ? kk : (kk - 3);
                const float* src = (g == 0) ? Wr : (g == 1) ? Wu : Wc;
                int off = ko*64 + d;
                a = v0 * src[off];
                a = fmaf(v1, src[KD + off], a);
                a = fmaf(v2, src[2*KD + off], a);
                a = fmaf(v3, src[3*KD + off], a);
                a = fmaf(v4, src[4*KD + off], a);
            }
            Wst[idx] = a;
        }
        for (int idx = tid; idx < 3*D_; idx += BLOCK) {
            int g = idx >> 6;
            int d = idx & 63;
            const float* src = (g == 0) ? brp : (g == 1) ? bup : bcp;
            float a = v0 * src[d];
            a = fmaf(v1, src[D_ + d], a);
            a = fmaf(v2, src[2*D_ + d], a);
            a = fmaf(v3, src[3*D_ + d], a);
            a = fmaf(v4, src[4*D_ + d], a);
            beff_s[idx] = a;
        }
    }

    // ===== P2b: inv_tot, P/Q transpose, zero h0, init persistent state =====
    {
        for (int k = tid; k < 32; k += BLOCK) {
            int idx = bid*32 + k;
            int b = idx >> 7;
            int n = idx & 127;
            float s = 0.0f;
            for (int t = 0; t < T_; t++) s += mask[(b*T_ + t)*N_ + n];
            g_invtot[idx] = 1.0f / (s + 1.0f);
        }
        for (int idx = bid*BLOCK + tid; idx < N_*N_; idx += GRID*BLOCK) {
            int j = idx >> 7, i = idx & 127;
            float a = adjI[i*N_ + j];
            g_P[idx] = a;
            g_Q[idx] = a * rarW[i*N_ + j];
        }
        for (int idx = bid*BLOCK + tid; idx < HSZ; idx += GRID*BLOCK)
            g_hbuf[idx] = 0.0f;
        for (int idx = tid; idx < B_*D_; idx += BLOCK) hsB[idx] = 0.0f;
        for (int idx = tid; idx < B_*16; idx += BLOCK) {
            int b = idx >> 4, qq = idx & 15;
            *(float4*)(zcs + b*KR + qq*4) =
                *(const float4*)(obs + (size_t)((b*T_)*N_ + n_node)*D_ + qq*4);
        }
        if (tid < 32) {
            float* zr = zcs + tid*KR;
            zr[65] = 0.0f; zr[66] = 0.0f; zr[67] = 0.0f;
        }
    }
    grid_barrier();
    if (tid < 32) {
        zcs[tid*KR + 64] =
            0.5f * tanhfast(avg[(tid*T_)*N_ + n_node] * g_invtot[tid*N_ + n_node]);
    }
    __syncthreads();

    // ========== time loop ==========
    for (int t = 0; t < T_; t++) {
        const float* hprev = g_hbuf + (t & 1) * HSZ;
        float*       hnext = g_hbuf + ((t + 1) & 1) * HSZ;

        // ---------------- Phase A ----------------
        {
            const int b = bid >> 2;
            const int q = bid & 3;
            float* feat = scrU + 0;
            float* wT   = scrU + 16896;
            float* rsv  = scrU + 20992;
            int*   list = (int*)(scrU + 21120);
            int*   cnt  = (int*)(scrU + 21248);

            if (tid < 128) {
                float m = mask[(b*T_ + t)*N_ + tid];
                rsv[tid] = 0.5f * tanhfast(avg[(b*T_ + t)*N_ + tid] * g_invtot[b*N_ + tid]);
                bool ob = (m != 0.0f);
                unsigned msk = __ballot_sync(0xffffffffu, ob);
                if (lane == 0) { cnt[warp] = __popc(msk); ((unsigned*)cnt)[4 + warp] = msk; }
            }
            __syncthreads();
            const int nobs = cnt[0] + cnt[1] + cnt[2] + cnt[3];
            if (tid < 128) {
                unsigned msk = ((unsigned*)cnt)[4 + warp];
                if ((msk >> lane) & 1u) {
                    int off = __popc(msk & ((1u << lane) - 1u));
                    for (int ww = 0; ww < warp; ww++) off += cnt[ww];
                    list[off] = tid;
                }
            }
            __syncthreads();

            const int lo  = (nobs * q) >> 2;
            const int hi  = (nobs * (q + 1)) >> 2;
            const int myn = hi - lo;

            for (int idx = tid; idx < nobs*16; idx += BLOCK) {
                int jc = idx >> 4, qq = idx & 15;
                int j = list[jc];
                *(float4*)(feat + jc*KR + qq*4) =
                    *(const float4*)(obs + (size_t)((b*T_ + t)*N_ + j)*D_ + qq*4);
            }
            for (int idx = tid; idx < nobs*16; idx += BLOCK) {
                int jc = idx >> 4, qq = idx & 15;
                int j = list[jc];
                *(float4*)(feat + jc*KR + 68 + qq*4) =
                    *(const float4*)(hprev + (size_t)(b*N_ + j)*D_ + qq*4);
            }
            if (tid < nobs) {
                float* fr = feat + tid*KR;
                fr[64] = rsv[list[tid]];
                fr[65] = 0.0f; fr[66] = 0.0f; fr[67] = 0.0f;
            }
            {
                int jc0 = warp;
                int ic  = lane;
                int i   = (ic < myn) ? list[lo + ic] : 0;
                float rsi = rsv[i];
                bool valid = (ic < myn);
                for (int jc = jc0; jc < nobs; jc += 32) {
                    int j = list[jc];
                    float wv = 0.0f;
                    if (valid) {
                        if (j == i) wv = 1.0f;
                        else wv = g_P[j*N_ + i] - g_Q[j*N_ + i] * fabsf(rsi - rsv[j]);
                    }
                    wT[jc*32 + ic] = wv;
                }
            }
            __syncthreads();

            const int RG2 = (myn + 1) >> 1;
            for (int tt = tid; tt < RG2*66; tt += BLOCK) {
                int rg = tt / 66;
                int e  = tt - rg*66;
                int c0 = e*2;
                const float* wp = wT + rg*2;
                const float* fp = feat + c0;
                float ax = 0.f, ay = 0.f, bx = 0.f, by = 0.f;
                #pragma unroll 4
                for (int jc = 0; jc < nobs; jc++) {
                    float2 w2 = *(const float2*)(wp + jc*32);
                    float2 f2 = *(const float2*)(fp + jc*KR);
                    ax = fmaf(w2.x, f2.x, ax); ay = fmaf(w2.x, f2.y, ay);
                    bx = fmaf(w2.y, f2.x, bx); by = fmaf(w2.y, f2.y, by);
                }
                int ic0 = rg*2;
                {
                    int i = list[lo + ic0];
                    *(float2*)&g_comb[(size_t)(b*N_ + i)*KR + c0] = make_float2(ax, ay);
                }
                if (ic0 + 1 < myn) {
                    int i1 = list[lo + ic0 + 1];
                    *(float2*)&g_comb[(size_t)(b*N_ + i1)*KR + c0] = make_float2(bx, by);
                }
            }
        }
        grid_barrier();

        // ---------------- Phase B ----------------
        {
            const int n = n_node;

            if (tid < 32) {
                int b = tid;
                float m = mask[(b*T_ + t)*N_ + n];
                lenS[b] = lengths[b];
                bool ob = (m != 0.0f);
                unsigned msk = __ballot_sync(0xffffffffu, ob);
                unsigned msku = ~msk;
                if (ob) listB[__popc(msk & ((1u << tid) - 1u))] = b;
                else    listU[__popc(msku & ((1u << tid) - 1u))] = b;
                if (tid == 0) *pnB = __popc(msk);
            }
            __syncthreads();
            const int nB  = *pnB;
            const int BG4 = (nB + 3) >> 2;

            for (int idx = tid; idx < nB*33; idx += BLOCK) {
                int bc = idx / 33;
                int qq = idx - bc*33;
                int b  = listB[bc];
                *(float4*)(combs + b*KR + qq*4) =
                    *(const float4*)(g_comb + (size_t)(b*N_ + n)*KR + qq*4);
            }
            __syncthreads();

            const int dgrp = lane >> 1;
            const int ks   = lane & 1;
            const int d0   = dgrp * 4;

            // ---- pass1: warps [0,2*BG4) r/u;  [2*BG4,3*BG4) candx ----
            if (warp < 3*BG4 && nB > 0) {
                int isRU = (warp < 2*BG4);
                int g, bgrp;
                const float* cbase;
                int k2lo, k2hi;
                if (isRU) {
                    g = warp & 1; bgrp = warp >> 1;
                    cbase = combs;
                    k2lo = ks ? 33 : 0;  k2hi = ks ? 66 : 33;
                } else {
                    g = 2; bgrp = warp - 2*BG4;
                    cbase = zcs;                     // candx: raw [x|rs|pads]
                    k2lo = ks ? 17 : 0;  k2hi = ks ? 34 : 17;   // k 0..67 (pads zero)
                }
                int bb[4];
                #pragma unroll
                for (int i = 0; i < 4; i++) bb[i] = listB[min(bgrp*4 + i, nB - 1)];
                const float* Wg = Wst + g*KD132;
                float acc[4][4];
                #pragma unroll
                for (int i = 0; i < 4; i++)
                    #pragma unroll
                    for (int j = 0; j < 4; j++) acc[i][j] = 0.0f;

                const float* c0p = cbase + bb[0]*KR;
                const float* c1p = cbase + bb[1]*KR;
                const float* c2p = cbase + bb[2]*KR;
                const float* c3p = cbase + bb[3]*KR;
                #pragma unroll 2
                for (int k2 = k2lo; k2 < k2hi; k2++) {
                    float2 c0 = *(const float2*)(c0p + 2*k2);
                    float2 c1 = *(const float2*)(c1p + 2*k2);
                    float2 c2 = *(const float2*)(c2p + 2*k2);
                    float2 c3 = *(const float2*)(c3p + 2*k2);
                    float4 wA = *(const float4*)(Wg + (2*k2)*64 + d0);
                    float4 wB = *(const float4*)(Wg + (2*k2 + 1)*64 + d0);
                    acc[0][0] = fmaf(c0.x, wA.x, acc[0][0]); acc[0][0] = fmaf(c0.y, wB.x, acc[0][0]);
                    acc[0][1] = fmaf(c0.x, wA.y, acc[0][1]); acc[0][1] = fmaf(c0.y, wB.y, acc[0][1]);
                    acc[0][2] = fmaf(c0.x, wA.z, acc[0][2]); acc[0][2] = fmaf(c0.y, wB.z, acc[0][2]);
                    acc[0][3] = fmaf(c0.x, wA.w, acc[0][3]); acc[0][3] = fmaf(c0.y, wB.w, acc[0][3]);
                    acc[1][0] = fmaf(c1.x, wA.x, acc[1][0]); acc[1][0] = fmaf(c1.y, wB.x, acc[1][0]);
                    acc[1][1] = fmaf(c1.x, wA.y, acc[1][1]); acc[1][1] = fmaf(c1.y, wB.y, acc[1][1]);
                    acc[1][2] = fmaf(c1.x, wA.z, acc[1][2]); acc[1][2] = fmaf(c1.y, wB.z, acc[1][2]);
                    acc[1][3] = fmaf(c1.x, wA.w, acc[1][3]); acc[1][3] = fmaf(c1.y, wB.w, acc[1][3]);
                    acc[2][0] = fmaf(c2.x, wA.x, acc[2][0]); acc[2][0] = fmaf(c2.y, wB.x, acc[2][0]);
                    acc[2][1] = fmaf(c2.x, wA.y, acc[2][1]); acc[2][1] = fmaf(c2.y, wB.y, acc[2][1]);
                    acc[2][2] = fmaf(c2.x, wA.z, acc[2][2]); acc[2][2] = fmaf(c2.y, wB.z, acc[2][2]);
                    acc[2][3] = fmaf(c2.x, wA.w, acc[2][3]); acc[2][3] = fmaf(c2.y, wB.w, acc[2][3]);
                    acc[3][0] = fmaf(c3.x, wA.x, acc[3][0]); acc[3][0] = fmaf(c3.y, wB.x, acc[3][0]);
                    acc[3][1] = fmaf(c3.x, wA.y, acc[3][1]); acc[3][1] = fmaf(c3.y, wB.y, acc[3][1]);
                    acc[3][2] = fmaf(c3.x, wA.z, acc[3][2]); acc[3][2] = fmaf(c3.y, wB.z, acc[3][2]);
                    acc[3][3] = fmaf(c3.x, wA.w, acc[3][3]); acc[3][3] = fmaf(c3.y, wB.w, acc[3][3]);
                }
                // combine ks halves (partner lane = lane^1)
                #pragma unroll
                for (int i = 0; i < 4; i++)
                    #pragma unroll
                    for (int j = 0; j < 4; j++)
                        acc[i][j] += __shfl_xor_sync(0xffffffffu, acc[i][j], 1);

                if (ks == 0) {
                    float4 bias = *(const float4*)(beff_s + g*64 + d0);
                    #pragma unroll
                    for (int i = 0; i < 4; i++) {
                        int b = bb[i];
                        float4 v = make_float4(acc[i][0] + bias.x, acc[i][1] + bias.y,
                                               acc[i][2] + bias.z, acc[i][3] + bias.w);
                        if (g == 0) {
                            float4 h = *(const float4*)(hsB + b*64 + d0);
                            *(float4*)(zcs + b*KR + 68 + d0) =
                                make_float4(sigfast(v.x)*h.x, sigfast(v.y)*h.y,
                                            sigfast(v.z)*h.z, sigfast(v.w)*h.w);
                        } else if (g == 1) {
                            *(float4*)(usB + b*64 + d0) =
                                make_float4(sigfast(v.x), sigfast(v.y),
                                            sigfast(v.z), sigfast(v.w));
                        } else {
                            *(float4*)(cxsB + b*64 + d0) = v;
                        }
                    }
                }
            }
            __syncthreads();

            // ---- pass2: warps [0,BG4) candh; rest carry unobserved ----
            if (warp < BG4 && nB > 0) {
                int bgrp = warp;
                int bb[4];
                #pragma unroll
                for (int i = 0; i < 4; i++) bb[i] = listB[min(bgrp*4 + i, nB - 1)];
                const float* Wg = Wst + 2*KD132;
                int k2lo = ks ? 50 : 34;    // k 68..131
                int k2hi = ks ? 66 : 50;
                float acc[4][4];
                #pragma unroll
                for (int i = 0; i < 4; i++)
                    #pragma unroll
                    for (int j = 0; j < 4; j++) acc[i][j] = 0.0f;
                const float* c0p = zcs + bb[0]*KR;
                const float* c1p = zcs + bb[1]*KR;
                const float* c2p = zcs + bb[2]*KR;
                const float* c3p = zcs + bb[3]*KR;
                #pragma unroll 2
                for (int k2 = k2lo; k2 < k2hi; k2++) {
                    float2 c0 = *(const float2*)(c0p + 2*k2);
                    float2 c1 = *(const float2*)(c1p + 2*k2);
                    float2 c2 = *(const float2*)(c2p + 2*k2);
                    float2 c3 = *(const float2*)(c3p + 2*k2);
                    float4 wA = *(const float4*)(Wg + (2*k2)*64 + d0);
                    float4 wB = *(const float4*)(Wg + (2*k2 + 1)*64 + d0);
                    acc[0][0] = fmaf(c0.x, wA.x, acc[0][0]); acc[0][0] = fmaf(c0.y, wB.x, acc[0][0]);
                    acc[0][1] = fmaf(c0.x, wA.y, acc[0][1]); acc[0][1] = fmaf(c0.y, wB.y, acc[0][1]);
                    acc[0][2] = fmaf(c0.x, wA.z, acc[0][2]); acc[0][2] = fmaf(c0.y, wB.z, acc[0][2]);
                    acc[0][3] = fmaf(c0.x, wA.w, acc[0][3]); acc[0][3] = fmaf(c0.y, wB.w, acc[0][3]);
                    acc[1][0] = fmaf(c1.x, wA.x, acc[1][0]); acc[1][0] = fmaf(c1.y, wB.x, acc[1][0]);
                    acc[1][1] = fmaf(c1.x, wA.y, acc[1][1]); acc[1][1] = fmaf(c1.y, wB.y, acc[1][1]);
                    acc[1][2] = fmaf(c1.x, wA.z, acc[1][2]); acc[1][2] = fmaf(c1.y, wB.z, acc[1][2]);
                    acc[1][3] = fmaf(c1.x, wA.w, acc[1][3]); acc[1][3] = fmaf(c1.y, wB.w, acc[1][3]);
                    acc[2][0] = fmaf(c2.x, wA.x, acc[2][0]); acc[2][0] = fmaf(c2.y, wB.x, acc[2][0]);
                    acc[2][1] = fmaf(c2.x, wA.y, acc[2][1]); acc[2][1] = fmaf(c2.y, wB.y, acc[2][1]);
                    acc[2][2] = fmaf(c2.x, wA.z, acc[2][2]); acc[2][2] = fmaf(c2.y, wB.z, acc[2][2]);
                    acc[2][3] = fmaf(c2.x, wA.w, acc[2][3]); acc[2][3] = fmaf(c2.y, wB.w, acc[2][3]);
                    acc[3][0] = fmaf(c3.x, wA.x, acc[3][0]); acc[3][0] = fmaf(c3.y, wB.x, acc[3][0]);
                    acc[3][1] = fmaf(c3.x, wA.y, acc[3][1]); acc[3][1] = fmaf(c3.y, wB.y, acc[3][1]);
                    acc[3][2] = fmaf(c3.x, wA.z, acc[3][2]); acc[3][2] = fmaf(c3.y, wB.z, acc[3][2]);
                    acc[3][3] = fmaf(c3.x, wA.w, acc[3][3]); acc[3][3] = fmaf(c3.y, wB.w, acc[3][3]);
                }
                #pragma unroll
                for (int i = 0; i < 4; i++)
                    #pragma unroll
                    for (int j = 0; j < 4; j++)
                        acc[i][j] += __shfl_xor_sync(0xffffffffu, acc[i][j], 1);

                if (ks == 0) {
                    #pragma unroll
                    for (int i = 0; i < 4; i++) {
                        int b = bb[i];
                        float4 cx = *(const float4*)(cxsB + b*64 + d0);
                        float4 h1 = *(const float4*)(zcs + b*KR + 68 + d0);
                        float4 u  = *(const float4*)(usB + b*64 + d0);
                        float4 v;
                        v.x = h1.x + u.x*(tanhfast(acc[i][0] + cx.x) - h1.x);
                        v.y = h1.y + u.y*(tanhfast(acc[i][1] + cx.y) - h1.y);
                        v.z = h1.z + u.z*(tanhfast(acc[i][2] + cx.z) - h1.z);
                        v.w = h1.w + u.w*(tanhfast(acc[i][3] + cx.w) - h1.w);
                        *(float4*)(hnext + (size_t)(b*N_ + n)*D_ + d0) = v;
                        *(float4*)(hsB + b*64 + d0) = v;
                        if (t == lenS[b] - 1)
                            *(float4*)(out + (size_t)(b*N_ + n)*D_ + d0) = v;
                    }
                }
            } else if (warp >= BG4) {
                int w2 = warp - BG4;
                int nU = B_ - nB;
                int pairs = (nU + 1) >> 1;
                if (w2 < pairs) {
                    int iu = w2 * 2;
                    int dd = lane * 2;
                    #pragma unroll
                    for (int rep = 0; rep < 2; rep++) {
                        if (iu + rep < nU) {
                            int b = listU[iu + rep];
                            float2 v = *(const float2*)(hsB + b*64 + dd);
                            *(float2*)(hnext + (size_t)(b*N_ + n)*D_ + dd) = v;
                            if (t == lenS[b] - 1)
                                *(float2*)(out + (size_t)(b*N_ + n)*D_ + dd) = v;
                        }
                    }
                }
            }
            // prefetch next step zcs x + rs (writes zcs[.][0..64], candh reads [68..] — disjoint)
            if (t + 1 < T_) {
                for (int idx = tid; idx < B_*16; idx += BLOCK) {
                    int b = idx >> 4, qq = idx & 15;
                    *(float4*)(zcs + b*KR + qq*4) =
                        *(const float4*)(obs + (size_t)((b*T_ + t + 1)*N_ + n)*D_ + qq*4);
                }
                if (tid < 32) {
                    zcs[tid*KR + 64] =
                        0.5f * tanhfast(avg[(tid*T_ + t + 1)*N_ + n] * g_invtot[tid*N_ + n]);
                }
            }
        }
        grid_barrier();
    }
}

extern "C" void kernel_launch(void* const* d_in, const int* in_sizes, int n_in,
                              void* d_out, int out_size) {
    const float* obs     = (const float*)d_in[0];
    const float* mask    = (const float*)d_in[2];
    const int*   lengths = (const int*)d_in[5];
    const float* avg     = (const float*)d_in[6];
    const float* vpe     = (const float*)d_in[7];
    const float* rarW    = (const float*)d_in[8];
    const float* adjI    = (const float*)d_in[9];
    const float* W1      = (const float*)d_in[10];
    const float* b1      = (const float*)d_in[11];
    const float* W2      = (const float*)d_in[12];
    const float* b2      = (const float*)d_in[13];
    const float* Wu      = (const float*)d_in[14];
    const float* bu      = (const float*)d_in[15];
    const float* Wr      = (const float*)d_in[16];
    const float* br      = (const float*)d_in[17];
    const float* Wc      = (const float*)d_in[18];
    const float* bc      = (const float*)d_in[19];
    float* out = (float*)d_out;

    cudaFuncSetAttribute(cgrnn_persistent,
                         cudaFuncAttributeMaxDynamicSharedMemorySize, SMEM_BYTES);
    cgrnn_persistent<<<GRID, BLOCK, SMEM_BYTES>>>(
        obs, mask, lengths, avg, vpe, rarW, adjI,
        W1, b1, W2, b2, Wr, br, Wu, bu, Wc, bc, out);
}